// round 14
// baseline (speedup 1.0000x reference)
#include <cuda_runtime.h>
#include <cuda_fp16.h>
#include <stdint.h>

// Equivariant linear via block-diagonal GEMMs, fp16 2-term emulation on
// m16n8k16 tensor cores.
//   w = wh + wl (fp16 pair, pre-scaled by 1/sqrt(mul); exact to ~2^-21)
//   x rounded once to fp16 (10-bit mantissa -> rel err ~2e-4, gate is 1e-3)
//   acc = wh*x + wl*x   (fp32 accumulate)
//  - W: pre-split fp16 (hi,lo) globals -> smem via cp.async, 2-stage pipeline.
//  - x, D=1 : LDG f32 -> regs (chunk ahead), cvt once -> fp16 smem [n][k];
//             B fragments via paired ldmatrix.x4.
//  - x, D>1 : raw f32 rows via cp.async 2-stage; cvt at B-fragment build.
// Blocks (mul, d, x_off, w_off):
//   (256,1,0,0) (128,3,256,65536) (64,5,640,81920) (32,7,960,86016)

#define FEAT 1184
#define BATCH_N 131072
#define NT 256
#define W_DIM 87040

__device__ __half g_wh[W_DIM];
__device__ __half g_wl[W_DIM];

// ---------------- helpers ----------------
__device__ __forceinline__ void cp16(uint32_t saddr, const void* gaddr) {
    asm volatile("cp.async.ca.shared.global [%0], [%1], 16;" :: "r"(saddr), "l"(gaddr));
}
__device__ __forceinline__ void ldsm4(unsigned* r, uint32_t a) {
    asm volatile("ldmatrix.sync.aligned.m8n8.x4.shared.b16 {%0,%1,%2,%3}, [%4];"
        : "=r"(r[0]), "=r"(r[1]), "=r"(r[2]), "=r"(r[3]) : "r"(a));
}
__device__ __forceinline__ void mma16(float* d, const unsigned* a, const unsigned* b) {
    asm volatile("mma.sync.aligned.m16n8k16.row.col.f32.f16.f16.f32 "
        "{%0,%1,%2,%3}, {%4,%5,%6,%7}, {%8,%9}, {%0,%1,%2,%3};"
        : "+f"(d[0]), "+f"(d[1]), "+f"(d[2]), "+f"(d[3])
        : "r"(a[0]), "r"(a[1]), "r"(a[2]), "r"(a[3]), "r"(b[0]), "r"(b[1]));
}
// pack two floats -> half2 word {lo=v0, hi=v1} (v0 at lower k)
__device__ __forceinline__ unsigned cvt2h(float v0, float v1) {
    unsigned r;
    asm("cvt.rn.f16x2.f32 %0, %1, %2;" : "=r"(r) : "f"(v1), "f"(v0));
    return r;
}

__global__ void wsplit_kernel(const float* __restrict__ w) {
    int idx = blockIdx.x * NT + threadIdx.x;
    if (idx >= W_DIM) return;
    float c = (idx < 65536) ? 0.0625f
            : (idx < 81920) ? 0.08838834764831845f
            : (idx < 86016) ? 0.125f
                            : 0.17677669529663687f;
    float v = w[idx] * c;
    __half h = __float2half_rn(v);
    g_wh[idx] = h;
    g_wl[idx] = __float2half_rn(v - __half2float(h));
}

__host__ __device__ constexpr int cmax(int a, int b) { return a > b ? a : b; }
__host__ __device__ constexpr int csmb(int D, int MCTA, int NB, int KC) {
    int KSh = KC + 8;
    int SWB = 2 * MCTA * KSh * 2;
    if (D == 1) return 2 * SWB + (NB * KSh) * 2;      // single fp16 x array
    int SXB = NB * (KC * D + 4) * 4;
    int mainb = 2 * SWB + 2 * SXB;
    int epib = MCTA * (NB * D + 2) * 4;
    return cmax(mainb, epib);
}

template<int MUL, int D, int XO, int WO, int MCTA, int NB, int KC, int WM, int WN,
         int MINB>
__global__ __launch_bounds__(NT, MINB)
void eqlin5(const float* __restrict__ x, float* __restrict__ y)
{
    constexpr int NCOL = NB * D;
    constexpr int NCH  = MUL / KC;
    constexpr int KSh  = KC + 8;               // W (and RM-x) row stride, halves
    constexpr int XRS  = KC * D + 4;           // D>1 x f32 row stride
    constexpr bool RM  = (D == 1);
    constexpr int TMW  = MCTA / WM;
    constexpr int TNW  = NCOL / WN;
    constexpr int MF   = TMW / 16;
    constexpr int NF   = TNW / 8;
    static_assert(TMW % 16 == 0 && TNW % 8 == 0 && WM * WN * 32 == NT, "tiling");
    static_assert(KC % 16 == 0 && NCH >= 2, "kc");
    static_assert(!RM || NF % 2 == 0, "rm pairs");

    constexpr int SWB  = 2 * MCTA * KSh * 2;   // W bytes per stage (hi+lo)
    constexpr int XW   = NB * KSh;             // RM halves in x array
    constexpr int SXB  = NB * XRS * 4;         // D>1 x bytes per stage
    constexpr int SMB  = csmb(D, MCTA, NB, KC);
    static_assert(SMB <= 48 * 1024, "smem");
    constexpr int WSEG = 2 * MCTA * (KC / 8);  // W 16B segs per stage
    constexpr int XSEG = NB * KC * D / 4;      // D>1 x 16B segs per stage
    constexpr int CNT2 = RM ? NB * KC / (2 * NT) : 1;  // RM float2/thread/chunk
    static_assert(!RM || (NB * KC) % (2 * NT) == 0, "rm loader");
    constexpr int SN   = NCOL + 2;
    static_assert(RM || (NB * MCTA * D) % (4 * NT) == 0, "epilogue");

    extern __shared__ __align__(16) char buf[];
    const uint32_t bu = (uint32_t)__cvta_generic_to_shared(buf);
    const uint32_t xh_u = bu + 2 * SWB;        // RM: fp16 x array

    const int tid = threadIdx.x;
    const int v0  = blockIdx.x * MCTA;
    const int b0  = blockIdx.y * NB;
    const int wid = tid >> 5, lane = tid & 31;
    const int g = lane >> 2, tg = lane & 3;
    const int wm = wid % WM, wn = wid / WM;
    const int mb0 = wm * TMW, nb0 = wn * TNW;

    const int m_add = (lane & 7) + 8 * ((lane >> 3) & 1);   // A ldsm4 row
    const int k_add = 8 * (lane >> 4);                      // A ldsm4 col
    const int bq  = ((lane >> 4) << 3) + (lane & 7);        // B ldsm4 row (RM)
    const int bqc = ((lane >> 3) & 1) << 3;                 // B ldsm4 col (RM)

    int xoff[NF];                                           // D>1 x word offsets
    #pragma unroll
    for (int nf = 0; nf < NF; ++nf) {
        int n = nb0 + nf * 8 + g;
        xoff[nf] = RM ? 0 : (n / D) * XRS + (n % D);
    }

    float acc[MF][NF][4];
    #pragma unroll
    for (int mf = 0; mf < MF; ++mf)
        #pragma unroll
        for (int nf = 0; nf < NF; ++nf)
            #pragma unroll
            for (int q = 0; q < 4; ++q) acc[mf][nf][q] = 0.f;

    auto load_w = [&](int s, int ch) {
        const int u0 = ch * KC;
        const uint32_t wdst = bu + s * SWB;
        constexpr int WIT = (WSEG + NT - 1) / NT;
        #pragma unroll
        for (int t = 0; t < WIT; ++t) {
            int sid = tid + t * NT;
            if (WSEG % NT == 0 || sid < WSEG) {
                int arr = sid / (WSEG / 2), r = sid % (WSEG / 2);
                int m = r / (KC / 8), sg = r % (KC / 8);
                const __half* gp = (arr ? g_wl : g_wh)
                    + WO + (size_t)(v0 + m) * MUL + u0 + sg * 8;
                cp16(wdst + (uint32_t)(arr * MCTA * KSh + m * KSh + sg * 8) * 2u, gp);
            }
        }
    };

    // ---- compute one chunk (stage s)
    auto compute = [&](int s, const float* xp) {
        const uint32_t whu = bu + s * SWB;
        const uint32_t wlu = whu + (uint32_t)MCTA * KSh * 2u;
        #pragma unroll
        for (int k16 = 0; k16 < KC / 16; ++k16) {
            const int kk = k16 * 16;
            unsigned ah[MF][4], al[MF][4];
            #pragma unroll
            for (int mf = 0; mf < MF; ++mf) {
                uint32_t off = (uint32_t)((mb0 + mf * 16 + m_add) * KSh
                                          + kk + k_add) * 2u;
                ldsm4(ah[mf], whu + off);
                ldsm4(al[mf], wlu + off);
            }
            unsigned bh[NF][2];
            if (RM) {
                #pragma unroll
                for (int p = 0; p < NF / 2; ++p) {
                    uint32_t off = (uint32_t)((nb0 + p * 16 + bq) * KSh
                                              + kk + bqc) * 2u;
                    unsigned t4[4];
                    ldsm4(t4, xh_u + off);
                    bh[2*p][0] = t4[0]; bh[2*p][1] = t4[1];
                    bh[2*p+1][0] = t4[2]; bh[2*p+1][1] = t4[3];
                }
            } else {
                #pragma unroll
                for (int nf = 0; nf < NF; ++nf) {
                    const float* p = xp + xoff[nf] + (kk + 2 * tg) * D;
                    bh[nf][0] = cvt2h(p[0], p[D]);
                    bh[nf][1] = cvt2h(p[8 * D], p[9 * D]);
                }
            }
            #pragma unroll
            for (int mf = 0; mf < MF; ++mf)
                #pragma unroll
                for (int nf = 0; nf < NF; ++nf) {
                    mma16(acc[mf][nf], ah[mf], bh[nf]);
                    mma16(acc[mf][nf], al[mf], bh[nf]);
                }
        }
    };

    if (RM) {
        // ---- D=1 pipeline: W cp.async 2-stage; x LDG->reg->cvt->fp16 smem
        float2 xr[CNT2];
        auto ldg_x = [&](int ch, float2* r) {
            const int base = XO + ch * KC;
            #pragma unroll
            for (int t = 0; t < CNT2; ++t) {
                int f = 2 * (tid + t * NT);
                int bl = f / KC, rr = f % KC;
                r[t] = *(const float2*)(x + (size_t)(b0 + bl) * FEAT + base + rr);
            }
        };
        auto sts_x = [&](const float2* r) {
            #pragma unroll
            for (int t = 0; t < CNT2; ++t) {
                int f = 2 * (tid + t * NT);
                int bl = f / KC, rr = f % KC;
                uint32_t a = (uint32_t)(bl * KSh + rr) * 2u;
                *(unsigned*)((char*)buf + (xh_u - bu) + a) = cvt2h(r[t].x, r[t].y);
            }
        };

        load_w(0, 0);
        asm volatile("cp.async.commit_group;");
        ldg_x(0, xr);

        for (int ch = 0; ch < NCH; ++ch) {
            const int s = ch & 1;
            __syncthreads();
            if (ch + 1 < NCH) {
                load_w(s ^ 1, ch + 1);
                asm volatile("cp.async.commit_group;");
            }
            sts_x(xr);
            if (ch + 1 < NCH) ldg_x(ch + 1, xr);
            if (ch + 1 < NCH) asm volatile("cp.async.wait_group 1;" ::: "memory");
            else              asm volatile("cp.async.wait_group 0;" ::: "memory");
            __syncthreads();
            compute(s, nullptr);
        }

        // direct fragment stores; m (=v) is y's fast axis
        #pragma unroll
        for (int mf = 0; mf < MF; ++mf)
            #pragma unroll
            for (int nf = 0; nf < NF; ++nf) {
                int m = v0 + mb0 + mf * 16 + g;
                int n = b0 + nb0 + nf * 8 + 2 * tg;
                y[(size_t)n * FEAT + XO + m]           = acc[mf][nf][0];
                y[(size_t)(n + 1) * FEAT + XO + m]     = acc[mf][nf][1];
                y[(size_t)n * FEAT + XO + m + 8]       = acc[mf][nf][2];
                y[(size_t)(n + 1) * FEAT + XO + m + 8] = acc[mf][nf][3];
            }
    } else {
        // ---- D>1 pipeline: W + raw f32 x, both cp.async 2-stage
        auto load_x = [&](int s, int ch) {
            const uint32_t xdst = bu + 2 * SWB + s * SXB;
            const int base = XO + ch * KC * D;
            constexpr int XIT = (XSEG + NT - 1) / NT;
            #pragma unroll
            for (int t = 0; t < XIT; ++t) {
                int sid = tid + t * NT;
                if (XSEG % NT == 0 || sid < XSEG) {
                    int bl = sid / (KC * D / 4), sg = sid % (KC * D / 4);
                    const float* gp = x + (size_t)(b0 + bl) * FEAT + base + sg * 4;
                    cp16(xdst + (uint32_t)(bl * XRS + sg * 4) * 4u, gp);
                }
            }
        };

        load_w(0, 0); load_x(0, 0);
        asm volatile("cp.async.commit_group;");

        for (int ch = 0; ch < NCH; ++ch) {
            const int s = ch & 1;
            if (ch + 1 < NCH) {
                load_w(s ^ 1, ch + 1); load_x(s ^ 1, ch + 1);
                asm volatile("cp.async.commit_group;");
                asm volatile("cp.async.wait_group 1;" ::: "memory");
            } else {
                asm volatile("cp.async.wait_group 0;" ::: "memory");
            }
            __syncthreads();
            compute(s, (const float*)(buf + 2 * SWB + s * SXB));
            __syncthreads();
        }

        // stage via smem, write coalesced float4
        float* S = (float*)buf;
        #pragma unroll
        for (int mf = 0; mf < MF; ++mf)
            #pragma unroll
            for (int nf = 0; nf < NF; ++nf) {
                int mb = mb0 + mf * 16, nn = nb0 + nf * 8 + 2 * tg;
                S[(mb + g) * SN + nn]         = acc[mf][nf][0];
                S[(mb + g) * SN + nn + 1]     = acc[mf][nf][1];
                S[(mb + g + 8) * SN + nn]     = acc[mf][nf][2];
                S[(mb + g + 8) * SN + nn + 1] = acc[mf][nf][3];
            }
        __syncthreads();

        constexpr int ROW = MCTA * D;
        #pragma unroll
        for (int t = 0; t < NB * ROW / 4 / NT; ++t) {
            int f4 = (tid + t * NT) * 4;
            int bl = f4 / ROW, r = f4 % ROW;
            float4 o;
            o.x = S[((r + 0) / D) * SN + bl * D + (r + 0) % D];
            o.y = S[((r + 1) / D) * SN + bl * D + (r + 1) % D];
            o.z = S[((r + 2) / D) * SN + bl * D + (r + 2) % D];
            o.w = S[((r + 3) / D) * SN + bl * D + (r + 3) % D];
            *(float4*)(y + (size_t)(b0 + bl) * FEAT + XO + v0 * D + r) = o;
        }
    }
}

extern "C" void kernel_launch(void* const* d_in, const int* in_sizes, int n_in,
                              void* d_out, int out_size) {
    const float* x = (const float*)d_in[0];
    const float* w = (const float*)d_in[1];
    float* y = (float*)d_out;
    (void)in_sizes; (void)n_in; (void)out_size;

    wsplit_kernel<<<(W_DIM + NT - 1) / NT, NT>>>(w);

    //       MUL  D   XO    WO   MCTA  NB  KC WM WN MINB   grid(v, b)
    eqlin5<256, 1,   0,     0,  64, 128, 32, 2, 4, 2>
        <<<dim3(4, BATCH_N / 128), NT, csmb(1, 64, 128, 32)>>>(x, y);
    eqlin5<128, 3, 256, 65536,  64,  32, 32, 2, 4, 2>
        <<<dim3(2, BATCH_N / 32), NT, csmb(3, 64, 32, 32)>>>(x, y);
    eqlin5< 64, 5, 640, 81920,  64,  32, 16, 2, 4, 2>
        <<<dim3(1, BATCH_N / 32), NT, csmb(5, 64, 32, 16)>>>(x, y);
    eqlin5< 32, 7, 960, 86016,  32,  32, 16, 2, 4, 3>
        <<<dim3(1, BATCH_N / 32), NT, csmb(7, 32, 32, 16)>>>(x, y);
}

// round 15
// speedup vs baseline: 1.5999x; 1.5999x over previous
#include <cuda_runtime.h>
#include <cuda_fp16.h>
#include <stdint.h>

// Equivariant linear via block-diagonal GEMMs, plain fp16 GEMM on m16n8k16
// tensor cores with fp32 accumulation.
//   w rounded once to fp16 (pre-scaled by 1/sqrt(mul));  x rounded once to
//   fp16.  Each contributes ~2.1e-4 rel err; combined ~2.9e-4 (gate 1e-3).
//   (2-term fp16 w-split was tried: the residual tile is denormal in fp16 and
//    HMMA runs ~1.6x slower on denormal operands -> slower than 3-term bf16.)
//  - W: fp16 global -> smem via cp.async, 2-stage pipeline.
//  - x, D=1 : LDG f32 -> regs (chunk ahead), cvt once -> fp16 smem [n][k];
//             B fragments via paired ldmatrix.x4.
//  - x, D>1 : raw f32 rows via cp.async 2-stage; cvt at B-fragment build.
// Blocks (mul, d, x_off, w_off):
//   (256,1,0,0) (128,3,256,65536) (64,5,640,81920) (32,7,960,86016)

#define FEAT 1184
#define BATCH_N 131072
#define NT 256
#define W_DIM 87040

__device__ __half g_wh[W_DIM];

// ---------------- helpers ----------------
__device__ __forceinline__ void cp16(uint32_t saddr, const void* gaddr) {
    asm volatile("cp.async.ca.shared.global [%0], [%1], 16;" :: "r"(saddr), "l"(gaddr));
}
__device__ __forceinline__ void ldsm4(unsigned* r, uint32_t a) {
    asm volatile("ldmatrix.sync.aligned.m8n8.x4.shared.b16 {%0,%1,%2,%3}, [%4];"
        : "=r"(r[0]), "=r"(r[1]), "=r"(r[2]), "=r"(r[3]) : "r"(a));
}
__device__ __forceinline__ void mma16(float* d, const unsigned* a, const unsigned* b) {
    asm volatile("mma.sync.aligned.m16n8k16.row.col.f32.f16.f16.f32 "
        "{%0,%1,%2,%3}, {%4,%5,%6,%7}, {%8,%9}, {%0,%1,%2,%3};"
        : "+f"(d[0]), "+f"(d[1]), "+f"(d[2]), "+f"(d[3])
        : "r"(a[0]), "r"(a[1]), "r"(a[2]), "r"(a[3]), "r"(b[0]), "r"(b[1]));
}
// pack two floats -> half2 word {lo=v0, hi=v1} (v0 at lower k)
__device__ __forceinline__ unsigned cvt2h(float v0, float v1) {
    unsigned r;
    asm("cvt.rn.f16x2.f32 %0, %1, %2;" : "=r"(r) : "f"(v1), "f"(v0));
    return r;
}

__global__ void wsplit_kernel(const float* __restrict__ w) {
    int idx = blockIdx.x * NT + threadIdx.x;
    if (idx >= W_DIM) return;
    float c = (idx < 65536) ? 0.0625f
            : (idx < 81920) ? 0.08838834764831845f
            : (idx < 86016) ? 0.125f
                            : 0.17677669529663687f;
    g_wh[idx] = __float2half_rn(w[idx] * c);
}

__host__ __device__ constexpr int cmax(int a, int b) { return a > b ? a : b; }
__host__ __device__ constexpr int csmb(int D, int MCTA, int NB, int KC) {
    int KSh = KC + 8;
    int SWB = MCTA * KSh * 2;                         // one fp16 W array/stage
    if (D == 1) return 2 * SWB + (NB * KSh) * 2;      // single fp16 x array
    int SXB = NB * (KC * D + 4) * 4;
    int mainb = 2 * SWB + 2 * SXB;
    int epib = MCTA * (NB * D + 2) * 4;
    return cmax(mainb, epib);
}

template<int MUL, int D, int XO, int WO, int MCTA, int NB, int KC, int WM, int WN,
         int MINB>
__global__ __launch_bounds__(NT, MINB)
void eqlin6(const float* __restrict__ x, float* __restrict__ y)
{
    constexpr int NCOL = NB * D;
    constexpr int NCH  = MUL / KC;
    constexpr int KSh  = KC + 8;               // W (and RM-x) row stride, halves
    constexpr int XRS  = KC * D + 4;           // D>1 x f32 row stride
    constexpr bool RM  = (D == 1);
    constexpr int TMW  = MCTA / WM;
    constexpr int TNW  = NCOL / WN;
    constexpr int MF   = TMW / 16;
    constexpr int NF   = TNW / 8;
    static_assert(TMW % 16 == 0 && TNW % 8 == 0 && WM * WN * 32 == NT, "tiling");
    static_assert(KC % 16 == 0 && NCH >= 2, "kc");
    static_assert(!RM || NF % 2 == 0, "rm pairs");

    constexpr int SWB  = MCTA * KSh * 2;       // W bytes per stage
    constexpr int XW   = NB * KSh;             // RM halves in x array
    constexpr int SXB  = NB * XRS * 4;         // D>1 x bytes per stage
    constexpr int SMB  = csmb(D, MCTA, NB, KC);
    static_assert(SMB <= 48 * 1024, "smem");
    constexpr int WSEG = MCTA * (KC / 8);      // W 16B segs per stage
    constexpr int XSEG = NB * KC * D / 4;      // D>1 x 16B segs per stage
    constexpr int CNT2 = RM ? NB * KC / (2 * NT) : 1;  // RM float2/thread/chunk
    static_assert(!RM || (NB * KC) % (2 * NT) == 0, "rm loader");
    constexpr int SN   = NCOL + 2;
    static_assert(RM || (NB * MCTA * D) % (4 * NT) == 0, "epilogue");

    extern __shared__ __align__(16) char buf[];
    const uint32_t bu = (uint32_t)__cvta_generic_to_shared(buf);
    const uint32_t xh_u = bu + 2 * SWB;        // RM: fp16 x array

    const int tid = threadIdx.x;
    const int v0  = blockIdx.x * MCTA;
    const int b0  = blockIdx.y * NB;
    const int wid = tid >> 5, lane = tid & 31;
    const int g = lane >> 2, tg = lane & 3;
    const int wm = wid % WM, wn = wid / WM;
    const int mb0 = wm * TMW, nb0 = wn * TNW;

    const int m_add = (lane & 7) + 8 * ((lane >> 3) & 1);   // A ldsm4 row
    const int k_add = 8 * (lane >> 4);                      // A ldsm4 col
    const int bq  = ((lane >> 4) << 3) + (lane & 7);        // B ldsm4 row (RM)
    const int bqc = ((lane >> 3) & 1) << 3;                 // B ldsm4 col (RM)

    int xoff[NF];                                           // D>1 x word offsets
    #pragma unroll
    for (int nf = 0; nf < NF; ++nf) {
        int n = nb0 + nf * 8 + g;
        xoff[nf] = RM ? 0 : (n / D) * XRS + (n % D);
    }

    float acc[MF][NF][4];
    #pragma unroll
    for (int mf = 0; mf < MF; ++mf)
        #pragma unroll
        for (int nf = 0; nf < NF; ++nf)
            #pragma unroll
            for (int q = 0; q < 4; ++q) acc[mf][nf][q] = 0.f;

    auto load_w = [&](int s, int ch) {
        const int u0 = ch * KC;
        const uint32_t wdst = bu + s * SWB;
        constexpr int WIT = (WSEG + NT - 1) / NT;
        #pragma unroll
        for (int t = 0; t < WIT; ++t) {
            int sid = tid + t * NT;
            if (WSEG % NT == 0 || sid < WSEG) {
                int m = sid / (KC / 8), sg = sid % (KC / 8);
                const __half* gp = g_wh
                    + WO + (size_t)(v0 + m) * MUL + u0 + sg * 8;
                cp16(wdst + (uint32_t)(m * KSh + sg * 8) * 2u, gp);
            }
        }
    };

    // ---- compute one chunk (stage s)
    auto compute = [&](int s, const float* xp) {
        const uint32_t whu = bu + s * SWB;
        #pragma unroll
        for (int k16 = 0; k16 < KC / 16; ++k16) {
            const int kk = k16 * 16;
            unsigned ah[MF][4];
            #pragma unroll
            for (int mf = 0; mf < MF; ++mf) {
                uint32_t off = (uint32_t)((mb0 + mf * 16 + m_add) * KSh
                                          + kk + k_add) * 2u;
                ldsm4(ah[mf], whu + off);
            }
            unsigned bh[NF][2];
            if (RM) {
                #pragma unroll
                for (int p = 0; p < NF / 2; ++p) {
                    uint32_t off = (uint32_t)((nb0 + p * 16 + bq) * KSh
                                              + kk + bqc) * 2u;
                    unsigned t4[4];
                    ldsm4(t4, xh_u + off);
                    bh[2*p][0] = t4[0]; bh[2*p][1] = t4[1];
                    bh[2*p+1][0] = t4[2]; bh[2*p+1][1] = t4[3];
                }
            } else {
                #pragma unroll
                for (int nf = 0; nf < NF; ++nf) {
                    const float* p = xp + xoff[nf] + (kk + 2 * tg) * D;
                    bh[nf][0] = cvt2h(p[0], p[D]);
                    bh[nf][1] = cvt2h(p[8 * D], p[9 * D]);
                }
            }
            #pragma unroll
            for (int mf = 0; mf < MF; ++mf)
                #pragma unroll
                for (int nf = 0; nf < NF; ++nf)
                    mma16(acc[mf][nf], ah[mf], bh[nf]);
        }
    };

    if (RM) {
        // ---- D=1 pipeline: W cp.async 2-stage; x LDG->reg->cvt->fp16 smem
        float2 xr[CNT2];
        auto ldg_x = [&](int ch, float2* r) {
            const int base = XO + ch * KC;
            #pragma unroll
            for (int t = 0; t < CNT2; ++t) {
                int f = 2 * (tid + t * NT);
                int bl = f / KC, rr = f % KC;
                r[t] = *(const float2*)(x + (size_t)(b0 + bl) * FEAT + base + rr);
            }
        };
        auto sts_x = [&](const float2* r) {
            #pragma unroll
            for (int t = 0; t < CNT2; ++t) {
                int f = 2 * (tid + t * NT);
                int bl = f / KC, rr = f % KC;
                uint32_t a = (uint32_t)(bl * KSh + rr) * 2u;
                *(unsigned*)((char*)buf + (xh_u - bu) + a) = cvt2h(r[t].x, r[t].y);
            }
        };

        load_w(0, 0);
        asm volatile("cp.async.commit_group;");
        ldg_x(0, xr);

        for (int ch = 0; ch < NCH; ++ch) {
            const int s = ch & 1;
            __syncthreads();
            if (ch + 1 < NCH) {
                load_w(s ^ 1, ch + 1);
                asm volatile("cp.async.commit_group;");
            }
            sts_x(xr);
            if (ch + 1 < NCH) ldg_x(ch + 1, xr);
            if (ch + 1 < NCH) asm volatile("cp.async.wait_group 1;" ::: "memory");
            else              asm volatile("cp.async.wait_group 0;" ::: "memory");
            __syncthreads();
            compute(s, nullptr);
        }

        // direct fragment stores; m (=v) is y's fast axis
        #pragma unroll
        for (int mf = 0; mf < MF; ++mf)
            #pragma unroll
            for (int nf = 0; nf < NF; ++nf) {
                int m = v0 + mb0 + mf * 16 + g;
                int n = b0 + nb0 + nf * 8 + 2 * tg;
                y[(size_t)n * FEAT + XO + m]           = acc[mf][nf][0];
                y[(size_t)(n + 1) * FEAT + XO + m]     = acc[mf][nf][1];
                y[(size_t)n * FEAT + XO + m + 8]       = acc[mf][nf][2];
                y[(size_t)(n + 1) * FEAT + XO + m + 8] = acc[mf][nf][3];
            }
    } else {
        // ---- D>1 pipeline: W + raw f32 x, both cp.async 2-stage
        auto load_x = [&](int s, int ch) {
            const uint32_t xdst = bu + 2 * SWB + s * SXB;
            const int base = XO + ch * KC * D;
            constexpr int XIT = (XSEG + NT - 1) / NT;
            #pragma unroll
            for (int t = 0; t < XIT; ++t) {
                int sid = tid + t * NT;
                if (XSEG % NT == 0 || sid < XSEG) {
                    int bl = sid / (KC * D / 4), sg = sid % (KC * D / 4);
                    const float* gp = x + (size_t)(b0 + bl) * FEAT + base + sg * 4;
                    cp16(xdst + (uint32_t)(bl * XRS + sg * 4) * 4u, gp);
                }
            }
        };

        load_w(0, 0); load_x(0, 0);
        asm volatile("cp.async.commit_group;");

        for (int ch = 0; ch < NCH; ++ch) {
            const int s = ch & 1;
            if (ch + 1 < NCH) {
                load_w(s ^ 1, ch + 1); load_x(s ^ 1, ch + 1);
                asm volatile("cp.async.commit_group;");
                asm volatile("cp.async.wait_group 1;" ::: "memory");
            } else {
                asm volatile("cp.async.wait_group 0;" ::: "memory");
            }
            __syncthreads();
            compute(s, (const float*)(buf + 2 * SWB + s * SXB));
            __syncthreads();
        }

        // stage via smem, write coalesced float4
        float* S = (float*)buf;
        #pragma unroll
        for (int mf = 0; mf < MF; ++mf)
            #pragma unroll
            for (int nf = 0; nf < NF; ++nf) {
                int mb = mb0 + mf * 16, nn = nb0 + nf * 8 + 2 * tg;
                S[(mb + g) * SN + nn]         = acc[mf][nf][0];
                S[(mb + g) * SN + nn + 1]     = acc[mf][nf][1];
                S[(mb + g + 8) * SN + nn]     = acc[mf][nf][2];
                S[(mb + g + 8) * SN + nn + 1] = acc[mf][nf][3];
            }
        __syncthreads();

        constexpr int ROW = MCTA * D;
        #pragma unroll
        for (int t = 0; t < NB * ROW / 4 / NT; ++t) {
            int f4 = (tid + t * NT) * 4;
            int bl = f4 / ROW, r = f4 % ROW;
            float4 o;
            o.x = S[((r + 0) / D) * SN + bl * D + (r + 0) % D];
            o.y = S[((r + 1) / D) * SN + bl * D + (r + 1) % D];
            o.z = S[((r + 2) / D) * SN + bl * D + (r + 2) % D];
            o.w = S[((r + 3) / D) * SN + bl * D + (r + 3) % D];
            *(float4*)(y + (size_t)(b0 + bl) * FEAT + XO + v0 * D + r) = o;
        }
    }
}

extern "C" void kernel_launch(void* const* d_in, const int* in_sizes, int n_in,
                              void* d_out, int out_size) {
    const float* x = (const float*)d_in[0];
    const float* w = (const float*)d_in[1];
    float* y = (float*)d_out;
    (void)in_sizes; (void)n_in; (void)out_size;

    wsplit_kernel<<<(W_DIM + NT - 1) / NT, NT>>>(w);

    //       MUL  D   XO    WO   MCTA  NB  KC WM WN MINB   grid(v, b)
    eqlin6<256, 1,   0,     0,  64, 128, 32, 2, 4, 2>
        <<<dim3(4, BATCH_N / 128), NT, csmb(1, 64, 128, 32)>>>(x, y);
    eqlin6<128, 3, 256, 65536,  64,  32, 32, 2, 4, 2>
        <<<dim3(2, BATCH_N / 32), NT, csmb(3, 64, 32, 32)>>>(x, y);
    eqlin6< 64, 5, 640, 81920,  64,  32, 16, 2, 4, 2>
        <<<dim3(1, BATCH_N / 32), NT, csmb(5, 64, 32, 16)>>>(x, y);
    eqlin6< 32, 7, 960, 86016,  32,  32, 16, 2, 4, 3>
        <<<dim3(1, BATCH_N / 32), NT, csmb(7, 32, 32, 16)>>>(x, y);
}